// round 4
// baseline (speedup 1.0000x reference)
#include <cuda_runtime.h>
#include <cuda_bf16.h>
#include <cstdint>

#define MAXN 2048
#define MARGIN 0.2f

__device__ float  g_sq[MAXN];
__device__ float  g_t[MAXN][8];   // pos_dist + margin, padded to 8
__device__ double g_acc[4];       // sabs, prec_count, pos_sum, neg_sum(dn)

// ---------------------------------------------------------------------------
__global__ void zero_acc_kernel() {
    if (threadIdx.x < 4) g_acc[threadIdx.x] = 0.0;
}

// ---------------------------------------------------------------------------
// One warp per anchor: row norm + positive distances (direct diff form).
__global__ __launch_bounds__(256)
void prep_kernel(const float* __restrict__ x, const int* __restrict__ tg,
                 int N, int D) {
    const int warp = threadIdx.x >> 5;
    const int lane = threadIdx.x & 31;
    const int a    = blockIdx.x * 8 + warp;
    if (a >= N) return;
    const int lbl = tg[a];
    const int U   = D >> 5;          // chunks of 32

    float xa[8];
    float sq = 0.f;
    #pragma unroll
    for (int u = 0; u < 8; u++) {
        if (u < U) {
            xa[u] = x[(size_t)a * D + u * 32 + lane];
            sq += xa[u] * xa[u];
        } else xa[u] = 0.f;
    }
    #pragma unroll
    for (int o = 16; o > 0; o >>= 1) sq += __shfl_xor_sync(0xffffffffu, sq, o);
    if (lane == 0) g_sq[a] = sq;

    int np = 0;
    float possum = 0.f;
    for (int base = 0; base < N; base += 32) {
        int l = tg[base + lane];
        unsigned m = __ballot_sync(0xffffffffu, l == lbl);
        while (m) {
            int b = __ffs(m) - 1;
            m &= m - 1;
            int j = base + b;
            if (j == a || np >= 8) continue;
            float d2 = 0.f;
            #pragma unroll
            for (int u = 0; u < 8; u++) {
                if (u < U) {
                    float xj = x[(size_t)j * D + u * 32 + lane];
                    float df = xa[u] - xj;
                    d2 += df * df;
                }
            }
            #pragma unroll
            for (int o = 16; o > 0; o >>= 1) d2 += __shfl_xor_sync(0xffffffffu, d2, o);
            float pd = sqrtf(fmaxf(d2, 1e-12f));
            if (lane == 0) {
                g_t[a][np] = pd + MARGIN;
                possum += pd;
            }
            np++;
        }
    }
    if (lane == 0) {
        for (int p = np; p < 8; p++) g_t[a][p] = 0.f;
        atomicAdd(&g_acc[2], (double)possum);
    }
}

// ---------------------------------------------------------------------------
// tf32 mma.sync m16n8k8 helper.
__device__ __forceinline__ void mma_tf32(float* c, const uint32_t* a, const uint32_t* b) {
    asm volatile(
        "mma.sync.aligned.m16n8k8.row.col.f32.tf32.tf32.f32 "
        "{%0,%1,%2,%3}, {%4,%5,%6,%7}, {%8,%9}, {%0,%1,%2,%3};\n"
        : "+f"(c[0]), "+f"(c[1]), "+f"(c[2]), "+f"(c[3])
        : "r"(a[0]), "r"(a[1]), "r"(a[2]), "r"(a[3]), "r"(b[0]), "r"(b[1]));
}

// ---------------------------------------------------------------------------
// Fused symmetric dist+hinge: one 128x128 tile per block, upper triangle only.
// Each unordered pair (i<j) contributes BOTH anchor orientations.
__global__ __launch_bounds__(256)
void fused_kernel(const float* __restrict__ x, const int* __restrict__ tg,
                  const int* __restrict__ ni, int N, int D) {
    __shared__ float As[128][36];
    __shared__ float Bs[128][36];
    __shared__ float s_tA[128][8], s_tB[128][8];
    __shared__ float s_sqA[128], s_sqB[128];
    __shared__ int   s_lA[128], s_lB[128];
    __shared__ float s_red[3][8];
    __shared__ int   s_npos;

    const int tid  = threadIdx.x;
    const int lane = tid & 31;
    const int warp = tid >> 5;
    const int wm   = warp >> 2;
    const int wn   = warp & 3;
    const int g    = lane >> 2;
    const int q    = lane & 3;

    // decode triangular tile index (bx >= by)
    const int T = N >> 7;
    int by = 0, rem = blockIdx.x, rowlen = T;
    while (rem >= rowlen) { rem -= rowlen; by++; rowlen--; }
    const int bx = by + rem;
    const int rowBase = by * 128;
    const int colBase = bx * 128;
    const bool diag = (bx == by);

    // stage per-row metadata
    if (tid == 0) s_npos = ni[0] - 1;
    if (tid < 128) {
        s_sqA[tid] = g_sq[rowBase + tid];
        s_sqB[tid] = g_sq[colBase + tid];
        s_lA[tid]  = tg[rowBase + tid];
        s_lB[tid]  = tg[colBase + tid];
    }
    {
        int r = tid >> 1, h = tid & 1;
        ((float4*)s_tA[r])[h] = ((const float4*)g_t[rowBase + r])[h];
        ((float4*)s_tB[r])[h] = ((const float4*)g_t[colBase + r])[h];
    }

    float acc[4][4][4];
    #pragma unroll
    for (int mt = 0; mt < 4; mt++)
        #pragma unroll
        for (int nt = 0; nt < 4; nt++)
            #pragma unroll
            for (int r = 0; r < 4; r++) acc[mt][nt][r] = 0.f;

    for (int kc = 0; kc < D; kc += 32) {
        __syncthreads();
        for (int t = tid; t < 128 * 8; t += 256) {
            int r  = t >> 3;
            int c4 = (t & 7) << 2;
            *(float4*)&As[r][c4] = *(const float4*)&x[(size_t)(rowBase + r) * D + kc + c4];
            *(float4*)&Bs[r][c4] = *(const float4*)&x[(size_t)(colBase + r) * D + kc + c4];
        }
        __syncthreads();

        #pragma unroll
        for (int kk = 0; kk < 32; kk += 8) {
            uint32_t a[4][4];
            #pragma unroll
            for (int mt = 0; mt < 4; mt++) {
                int r0 = wm * 64 + mt * 16 + g;
                a[mt][0] = __float_as_uint(As[r0][kk + q]);
                a[mt][1] = __float_as_uint(As[r0 + 8][kk + q]);
                a[mt][2] = __float_as_uint(As[r0][kk + q + 4]);
                a[mt][3] = __float_as_uint(As[r0 + 8][kk + q + 4]);
            }
            uint32_t b[4][2];
            #pragma unroll
            for (int nt = 0; nt < 4; nt++) {
                int c0 = wn * 32 + nt * 8 + g;
                b[nt][0] = __float_as_uint(Bs[c0][kk + q]);
                b[nt][1] = __float_as_uint(Bs[c0][kk + q + 4]);
            }
            #pragma unroll
            for (int mt = 0; mt < 4; mt++)
                #pragma unroll
                for (int nt = 0; nt < 4; nt++)
                    mma_tf32(acc[mt][nt], a[mt], b[nt]);
        }
    }
    __syncthreads();

    // -------------------- epilogue: hinge statistics --------------------
    const int npos = s_npos;
    float sabs = 0.f, dn = 0.f;
    int pc = 0;

    if (npos == 7) {
        // hoist all 8 row t-vectors into registers
        float ta[8][7];
        float sqa[8];
        int   la[8];
        #pragma unroll
        for (int m8 = 0; m8 < 8; m8++) {
            int r = wm * 64 + (m8 >> 1) * 16 + (m8 & 1) * 8 + g;
            #pragma unroll
            for (int p = 0; p < 7; p++) ta[m8][p] = s_tA[r][p];
            sqa[m8] = s_sqA[r];
            la[m8]  = s_lA[r];
        }
        #pragma unroll
        for (int nt = 0; nt < 4; nt++) {
            #pragma unroll
            for (int v = 0; v < 2; v++) {
                int c = wn * 32 + nt * 8 + 2 * q + v;
                int j = colBase + c;
                float tb[7];
                #pragma unroll
                for (int p = 0; p < 7; p++) tb[p] = s_tB[c][p];
                float sqb = s_sqB[c];
                int   lb  = s_lB[c];
                #pragma unroll
                for (int mt = 0; mt < 4; mt++) {
                    #pragma unroll
                    for (int h = 0; h < 2; h++) {
                        int m8 = mt * 2 + h;
                        int i = rowBase + wm * 64 + mt * 16 + h * 8 + g;
                        if (diag && j <= i) continue;
                        if (la[m8] == lb) continue;
                        float d = sqrtf(fmaxf(sqa[m8] + sqb - 2.f * acc[mt][nt][h * 2 + v], 1e-12f));
                        dn += 2.f * d;
                        #pragma unroll
                        for (int p = 0; p < 7; p++) {
                            float dl = ta[m8][p] - d;
                            sabs += fabsf(dl);
                            pc += (dl < MARGIN);
                        }
                        #pragma unroll
                        for (int p = 0; p < 7; p++) {
                            float dl = tb[p] - d;
                            sabs += fabsf(dl);
                            pc += (dl < MARGIN);
                        }
                    }
                }
            }
        }
    } else {
        // generic fallback
        #pragma unroll
        for (int mt = 0; mt < 4; mt++) {
            #pragma unroll
            for (int h = 0; h < 2; h++) {
                int r = wm * 64 + mt * 16 + h * 8 + g;
                int i = rowBase + r;
                #pragma unroll
                for (int nt = 0; nt < 4; nt++) {
                    #pragma unroll
                    for (int v = 0; v < 2; v++) {
                        int c = wn * 32 + nt * 8 + 2 * q + v;
                        int j = colBase + c;
                        if (diag && j <= i) continue;
                        if (s_lA[r] == s_lB[c]) continue;
                        float d = sqrtf(fmaxf(s_sqA[r] + s_sqB[c] - 2.f * acc[mt][nt][h * 2 + v], 1e-12f));
                        dn += 2.f * d;
                        for (int p = 0; p < npos; p++) {
                            float dla = s_tA[r][p] - d;
                            sabs += fabsf(dla);
                            pc += (dla < MARGIN);
                            float dlb = s_tB[c][p] - d;
                            sabs += fabsf(dlb);
                            pc += (dlb < MARGIN);
                        }
                    }
                }
            }
        }
    }

    // block reduction of (sabs, dn, pc)
    float v3[3] = {sabs, dn, (float)pc};
    #pragma unroll
    for (int r = 0; r < 3; r++) {
        float s = v3[r];
        #pragma unroll
        for (int o = 16; o > 0; o >>= 1) s += __shfl_xor_sync(0xffffffffu, s, o);
        if (lane == 0) s_red[r][warp] = s;
    }
    __syncthreads();
    if (warp == 0 && lane < 3) {
        float s = 0.f;
        #pragma unroll
        for (int w = 0; w < 8; w++) s += s_red[lane][w];
        atomicAdd(&g_acc[lane == 0 ? 0 : (lane == 1 ? 3 : 1)],
                  (double)s);  // lane0->sabs(0), lane1->dn(3), lane2->pc(1)
    }
}

// ---------------------------------------------------------------------------
__global__ void finalize_kernel(const int* __restrict__ ni, int N, float* __restrict__ out) {
    if (threadIdx.x != 0 || blockIdx.x != 0) return;
    int K = ni[0];
    double npos = (double)(K - 1);
    double nneg = (double)(N - K);
    double sabs   = g_acc[0];
    double pc     = g_acc[1];
    double possum = g_acc[2];
    double dn     = g_acc[3];
    double T_total = possum + (double)N * npos * (double)MARGIN;
    double hinge   = 0.5 * (nneg * T_total - npos * dn + sabs);
    double cnt     = (double)N * npos * nneg;
    out[0] = (float)(hinge / cnt);
    out[1] = (float)(pc / cnt);
    out[2] = (float)(possum / ((double)N * npos));
    out[3] = (float)(dn / ((double)N * nneg));
}

// ---------------------------------------------------------------------------
extern "C" void kernel_launch(void* const* d_in, const int* in_sizes, int n_in,
                              void* d_out, int out_size) {
    const float* x  = (const float*)d_in[0];
    const int*   tg = (const int*)d_in[1];
    const int*   ni = (const int*)d_in[2];
    float*       out = (float*)d_out;

    const int N = in_sizes[1];
    const int D = in_sizes[0] / N;
    const int T = N / 128;
    const int nTiles = T * (T + 1) / 2;

    zero_acc_kernel<<<1, 32>>>();
    prep_kernel<<<(N + 7) / 8, 256>>>(x, tg, N, D);
    fused_kernel<<<nTiles, 256>>>(x, tg, ni, N, D);
    finalize_kernel<<<1, 32>>>(ni, N, out);
}

// round 5
// speedup vs baseline: 1.1649x; 1.1649x over previous
#include <cuda_runtime.h>
#include <cuda_bf16.h>
#include <cstdint>

#define MAXN 2048
#define MARGIN 0.2f

__device__ float  g_sq[MAXN];
__device__ float  g_t[MAXN][8];   // pos_dist + margin, padded to 8 (pads = 0)
__device__ double g_acc[4];       // [0]=sabs, [1]=prec_count, [2]=unused, [3]=dn

// ---------------------------------------------------------------------------
// One warp per anchor. Shared-staged labels -> cheap scan; batched positive dots.
// Block 0 also zeroes g_acc (safe: g_acc first read/written again in fused_kernel,
// which is stream-ordered after this kernel completes).
__global__ __launch_bounds__(256)
void prep_kernel(const float* __restrict__ x, const int* __restrict__ tg,
                 const int* __restrict__ ni, int N, int D) {
    __shared__ int s_tg[MAXN];
    __shared__ int s_j[8][8];

    const int tid = threadIdx.x;
    if (blockIdx.x == 0 && tid < 4) g_acc[tid] = 0.0;

    for (int t = tid; t < N; t += 256) s_tg[t] = tg[t];
    __syncthreads();

    const int warp = tid >> 5;
    const int lane = tid & 31;
    const int a    = blockIdx.x * 8 + warp;
    if (a >= N) return;

    const int lbl  = s_tg[a];
    const int U    = D >> 5;                 // 32-wide chunks (D=128 -> 4)
    const int want = min(ni[0] - 1, 8);

    // row vector + squared norm
    float xa[8];
    float sq = 0.f;
    #pragma unroll 4
    for (int u = 0; u < 8; u++) {
        if (u < U) {
            xa[u] = x[(size_t)a * D + u * 32 + lane];
            sq += xa[u] * xa[u];
        } else xa[u] = 0.f;
    }
    #pragma unroll
    for (int o = 16; o > 0; o >>= 1) sq += __shfl_xor_sync(0xffffffffu, sq, o);
    if (lane == 0) g_sq[a] = sq;

    // scan shared labels for positive indices (uniform control flow)
    int np = 0;
    for (int base = 0; base < N && np < want; base += 32) {
        int l = s_tg[base + lane];
        unsigned m = __ballot_sync(0xffffffffu, l == lbl);
        while (m && np < want) {
            int b = __ffs(m) - 1;
            m &= m - 1;
            int j = base + b;
            if (j != a) {
                if (lane == 0) s_j[warp][np] = j;
                np++;
            }
        }
    }
    __syncwarp();

    // batched positive distances: all loads issued up front (MLP), then reduce
    float d2[8];
    #pragma unroll
    for (int p = 0; p < 8; p++) d2[p] = 0.f;
    #pragma unroll
    for (int p = 0; p < 8; p++) {
        if (p < np) {
            const float* __restrict__ xj = x + (size_t)s_j[warp][p] * D;
            #pragma unroll 4
            for (int u = 0; u < 8; u++) {
                if (u < U) {
                    float df = xa[u] - xj[u * 32 + lane];
                    d2[p] += df * df;
                }
            }
        }
    }
    #pragma unroll
    for (int p = 0; p < 8; p++) {
        if (p < np) {
            float s = d2[p];
            #pragma unroll
            for (int o = 16; o > 0; o >>= 1) s += __shfl_xor_sync(0xffffffffu, s, o);
            d2[p] = s;
        }
    }
    if (lane == 0) {
        #pragma unroll
        for (int p = 0; p < 8; p++)
            g_t[a][p] = (p < np) ? sqrtf(fmaxf(d2[p], 1e-12f)) + MARGIN : 0.f;
    }
}

// ---------------------------------------------------------------------------
// tf32 mma.sync m16n8k8 helper.
__device__ __forceinline__ void mma_tf32(float* c, const uint32_t* a, const uint32_t* b) {
    asm volatile(
        "mma.sync.aligned.m16n8k8.row.col.f32.tf32.tf32.f32 "
        "{%0,%1,%2,%3}, {%4,%5,%6,%7}, {%8,%9}, {%0,%1,%2,%3};\n"
        : "+f"(c[0]), "+f"(c[1]), "+f"(c[2]), "+f"(c[3])
        : "r"(a[0]), "r"(a[1]), "r"(a[2]), "r"(a[3]), "r"(b[0]), "r"(b[1]));
}

// ---------------------------------------------------------------------------
// Fused symmetric dist+hinge: one 128x128 tile per block, upper triangle only.
// Each unordered pair (i<j) contributes BOTH anchor orientations.
__global__ __launch_bounds__(256)
void fused_kernel(const float* __restrict__ x, const int* __restrict__ tg,
                  const int* __restrict__ ni, int N, int D) {
    __shared__ float As[128][36];
    __shared__ float Bs[128][36];
    __shared__ float s_tA[128][8], s_tB[128][8];
    __shared__ float s_sqA[128], s_sqB[128];
    __shared__ int   s_lA[128], s_lB[128];
    __shared__ float s_red[3][8];
    __shared__ int   s_npos;

    const int tid  = threadIdx.x;
    const int lane = tid & 31;
    const int warp = tid >> 5;
    const int wm   = warp >> 2;
    const int wn   = warp & 3;
    const int g    = lane >> 2;
    const int q    = lane & 3;

    // decode triangular tile index (bx >= by)
    const int T = N >> 7;
    int by = 0, rem = blockIdx.x, rowlen = T;
    while (rem >= rowlen) { rem -= rowlen; by++; rowlen--; }
    const int bx = by + rem;
    const int rowBase = by * 128;
    const int colBase = bx * 128;
    const bool diag = (bx == by);

    // stage per-row metadata
    if (tid == 0) s_npos = ni[0] - 1;
    if (tid < 128) {
        s_sqA[tid] = g_sq[rowBase + tid];
        s_sqB[tid] = g_sq[colBase + tid];
        s_lA[tid]  = tg[rowBase + tid];
        s_lB[tid]  = tg[colBase + tid];
    }
    {
        int r = tid >> 1, h = tid & 1;
        ((float4*)s_tA[r])[h] = ((const float4*)g_t[rowBase + r])[h];
        ((float4*)s_tB[r])[h] = ((const float4*)g_t[colBase + r])[h];
    }

    float acc[4][4][4];
    #pragma unroll
    for (int mt = 0; mt < 4; mt++)
        #pragma unroll
        for (int nt = 0; nt < 4; nt++)
            #pragma unroll
            for (int r = 0; r < 4; r++) acc[mt][nt][r] = 0.f;

    for (int kc = 0; kc < D; kc += 32) {
        __syncthreads();
        for (int t = tid; t < 128 * 8; t += 256) {
            int r  = t >> 3;
            int c4 = (t & 7) << 2;
            *(float4*)&As[r][c4] = *(const float4*)&x[(size_t)(rowBase + r) * D + kc + c4];
            *(float4*)&Bs[r][c4] = *(const float4*)&x[(size_t)(colBase + r) * D + kc + c4];
        }
        __syncthreads();

        #pragma unroll
        for (int kk = 0; kk < 32; kk += 8) {
            uint32_t a[4][4];
            #pragma unroll
            for (int mt = 0; mt < 4; mt++) {
                int r0 = wm * 64 + mt * 16 + g;
                a[mt][0] = __float_as_uint(As[r0][kk + q]);
                a[mt][1] = __float_as_uint(As[r0 + 8][kk + q]);
                a[mt][2] = __float_as_uint(As[r0][kk + q + 4]);
                a[mt][3] = __float_as_uint(As[r0 + 8][kk + q + 4]);
            }
            uint32_t b[4][2];
            #pragma unroll
            for (int nt = 0; nt < 4; nt++) {
                int c0 = wn * 32 + nt * 8 + g;
                b[nt][0] = __float_as_uint(Bs[c0][kk + q]);
                b[nt][1] = __float_as_uint(Bs[c0][kk + q + 4]);
            }
            #pragma unroll
            for (int mt = 0; mt < 4; mt++)
                #pragma unroll
                for (int nt = 0; nt < 4; nt++)
                    mma_tf32(acc[mt][nt], a[mt], b[nt]);
        }
    }
    __syncthreads();

    // -------------------- epilogue: hinge statistics --------------------
    const int npos = s_npos;
    float sabs = 0.f, dn = 0.f;
    int pc = 0;

    if (npos == 7) {
        float ta[8][7];
        float sqa[8];
        int   la[8];
        #pragma unroll
        for (int m8 = 0; m8 < 8; m8++) {
            int r = wm * 64 + (m8 >> 1) * 16 + (m8 & 1) * 8 + g;
            #pragma unroll
            for (int p = 0; p < 7; p++) ta[m8][p] = s_tA[r][p];
            sqa[m8] = s_sqA[r];
            la[m8]  = s_lA[r];
        }
        #pragma unroll
        for (int nt = 0; nt < 4; nt++) {
            #pragma unroll
            for (int v = 0; v < 2; v++) {
                int c = wn * 32 + nt * 8 + 2 * q + v;
                int j = colBase + c;
                float tb[7];
                #pragma unroll
                for (int p = 0; p < 7; p++) tb[p] = s_tB[c][p];
                float sqb = s_sqB[c];
                int   lb  = s_lB[c];
                #pragma unroll
                for (int mt = 0; mt < 4; mt++) {
                    #pragma unroll
                    for (int h = 0; h < 2; h++) {
                        int m8 = mt * 2 + h;
                        int i = rowBase + wm * 64 + mt * 16 + h * 8 + g;
                        if (diag && j <= i) continue;
                        if (la[m8] == lb) continue;
                        float d = sqrtf(fmaxf(sqa[m8] + sqb - 2.f * acc[mt][nt][h * 2 + v], 1e-12f));
                        dn += 2.f * d;
                        #pragma unroll
                        for (int p = 0; p < 7; p++) {
                            float dl = ta[m8][p] - d;
                            sabs += fabsf(dl);
                            pc += (dl < MARGIN);
                        }
                        #pragma unroll
                        for (int p = 0; p < 7; p++) {
                            float dl = tb[p] - d;
                            sabs += fabsf(dl);
                            pc += (dl < MARGIN);
                        }
                    }
                }
            }
        }
    } else {
        #pragma unroll
        for (int mt = 0; mt < 4; mt++) {
            #pragma unroll
            for (int h = 0; h < 2; h++) {
                int r = wm * 64 + mt * 16 + h * 8 + g;
                int i = rowBase + r;
                #pragma unroll
                for (int nt = 0; nt < 4; nt++) {
                    #pragma unroll
                    for (int v = 0; v < 2; v++) {
                        int c = wn * 32 + nt * 8 + 2 * q + v;
                        int j = colBase + c;
                        if (diag && j <= i) continue;
                        if (s_lA[r] == s_lB[c]) continue;
                        float d = sqrtf(fmaxf(s_sqA[r] + s_sqB[c] - 2.f * acc[mt][nt][h * 2 + v], 1e-12f));
                        dn += 2.f * d;
                        for (int p = 0; p < npos; p++) {
                            float dla = s_tA[r][p] - d;
                            sabs += fabsf(dla);
                            pc += (dla < MARGIN);
                            float dlb = s_tB[c][p] - d;
                            sabs += fabsf(dlb);
                            pc += (dlb < MARGIN);
                        }
                    }
                }
            }
        }
    }

    // block reduction of (sabs, dn, pc)
    float v3[3] = {sabs, dn, (float)pc};
    #pragma unroll
    for (int r = 0; r < 3; r++) {
        float s = v3[r];
        #pragma unroll
        for (int o = 16; o > 0; o >>= 1) s += __shfl_xor_sync(0xffffffffu, s, o);
        if (lane == 0) s_red[r][warp] = s;
    }
    __syncthreads();
    if (warp == 0 && lane < 3) {
        float s = 0.f;
        #pragma unroll
        for (int w = 0; w < 8; w++) s += s_red[lane][w];
        atomicAdd(&g_acc[lane == 0 ? 0 : (lane == 1 ? 3 : 1)],
                  (double)s);  // lane0->sabs(0), lane1->dn(3), lane2->pc(1)
    }
}

// ---------------------------------------------------------------------------
// 256-thread finalize: recompute T_total = sum(g_t) (includes +margin on the
// N*npos real entries; pads are 0), then all four outputs.
__global__ __launch_bounds__(256)
void finalize_kernel(const int* __restrict__ ni, int N, float* __restrict__ out) {
    __shared__ double s_sum[8];
    const int tid  = threadIdx.x;
    const int lane = tid & 31;
    const int warp = tid >> 5;

    const float* __restrict__ tflat = (const float*)g_t;
    double s = 0.0;
    for (int t = tid; t < N * 8; t += 256) s += (double)tflat[t];
    #pragma unroll
    for (int o = 16; o > 0; o >>= 1) s += __shfl_xor_sync(0xffffffffu, s, o);
    if (lane == 0) s_sum[warp] = s;
    __syncthreads();

    if (tid == 0) {
        double T_total = 0.0;
        #pragma unroll
        for (int w = 0; w < 8; w++) T_total += s_sum[w];

        int K = ni[0];
        double npos = (double)(K - 1);
        double nneg = (double)(N - K);
        double sabs = g_acc[0];
        double pc   = g_acc[1];
        double dn   = g_acc[3];
        double possum = T_total - (double)N * npos * (double)MARGIN;
        double hinge  = 0.5 * (nneg * T_total - npos * dn + sabs);
        double cnt    = (double)N * npos * nneg;
        out[0] = (float)(hinge / cnt);
        out[1] = (float)(pc / cnt);
        out[2] = (float)(possum / ((double)N * npos));
        out[3] = (float)(dn / ((double)N * nneg));
    }
}

// ---------------------------------------------------------------------------
extern "C" void kernel_launch(void* const* d_in, const int* in_sizes, int n_in,
                              void* d_out, int out_size) {
    const float* x  = (const float*)d_in[0];
    const int*   tg = (const int*)d_in[1];
    const int*   ni = (const int*)d_in[2];
    float*       out = (float*)d_out;

    const int N = in_sizes[1];
    const int D = in_sizes[0] / N;
    const int T = N / 128;
    const int nTiles = T * (T + 1) / 2;

    prep_kernel<<<(N + 7) / 8, 256>>>(x, tg, ni, N, D);
    fused_kernel<<<nTiles, 256>>>(x, tg, ni, N, D);
    finalize_kernel<<<1, 256>>>(ni, N, out);
}

// round 6
// speedup vs baseline: 1.3116x; 1.1259x over previous
#include <cuda_runtime.h>
#include <cuda_bf16.h>
#include <cstdint>

#define MAXN 2048
#define MARGIN 0.2f

__device__ float  g_sq[MAXN];
__device__ float  g_t[MAXN][8];   // pos_dist + margin, padded to 8 (pads = 0)
__device__ double g_acc[4];       // [0]=sabs, [1]=prec_count, [2]=unused, [3]=dn

// ---------------------------------------------------------------------------
// One warp per anchor. Scan starts at the anchor's own 32-block and wraps, so
// with grouped labels it terminates in 1-2 iterations (still correct for any
// balanced layout). Block 0 zeroes g_acc (next reader is fused_kernel, which
// is stream-ordered after this kernel).
__global__ __launch_bounds__(256)
void prep_kernel(const float* __restrict__ x, const int* __restrict__ tg,
                 const int* __restrict__ ni, int N, int D) {
    __shared__ int s_j[8][8];

    const int tid = threadIdx.x;
    if (blockIdx.x == 0 && tid < 4) g_acc[tid] = 0.0;

    const int warp = tid >> 5;
    const int lane = tid & 31;
    const int a    = blockIdx.x * 8 + warp;
    if (a >= N) return;

    const int lbl  = tg[a];
    const int U    = D >> 5;                 // 32-wide chunks (D=128 -> 4)
    const int want = min(ni[0] - 1, 8);

    // row vector + squared norm
    float xa[8];
    float sq = 0.f;
    #pragma unroll 4
    for (int u = 0; u < 8; u++) {
        if (u < U) {
            xa[u] = x[(size_t)a * D + u * 32 + lane];
            sq += xa[u] * xa[u];
        } else xa[u] = 0.f;
    }
    #pragma unroll
    for (int o = 16; o > 0; o >>= 1) sq += __shfl_xor_sync(0xffffffffu, sq, o);
    if (lane == 0) g_sq[a] = sq;

    // wrap-scan for positive indices, starting at anchor's own block
    const int nBlk  = N >> 5;
    const int blk0  = a >> 5;
    int np = 0;
    for (int it = 0; it < nBlk && np < want; it++) {
        int base = ((blk0 + it) & (nBlk - 1)) << 5;   // N is a power of two
        int l = tg[base + lane];
        unsigned m = __ballot_sync(0xffffffffu, l == lbl);
        while (m && np < want) {
            int b = __ffs(m) - 1;
            m &= m - 1;
            int j = base + b;
            if (j != a) {
                if (lane == 0) s_j[warp][np] = j;
                np++;
            }
        }
    }
    __syncwarp();

    // batched positive distances: loads issued up front (MLP), then reduce
    float d2[8];
    #pragma unroll
    for (int p = 0; p < 8; p++) d2[p] = 0.f;
    #pragma unroll
    for (int p = 0; p < 8; p++) {
        if (p < np) {
            const float* __restrict__ xj = x + (size_t)s_j[warp][p] * D;
            #pragma unroll 4
            for (int u = 0; u < 8; u++) {
                if (u < U) {
                    float df = xa[u] - xj[u * 32 + lane];
                    d2[p] += df * df;
                }
            }
        }
    }
    #pragma unroll
    for (int p = 0; p < 8; p++) {
        if (p < np) {
            float s = d2[p];
            #pragma unroll
            for (int o = 16; o > 0; o >>= 1) s += __shfl_xor_sync(0xffffffffu, s, o);
            d2[p] = s;
        }
    }
    if (lane == 0) {
        #pragma unroll
        for (int p = 0; p < 8; p++)
            g_t[a][p] = (p < np) ? sqrtf(fmaxf(d2[p], 1e-12f)) + MARGIN : 0.f;
    }
}

// ---------------------------------------------------------------------------
__device__ __forceinline__ void mma_tf32(float* c, const uint32_t* a, const uint32_t* b) {
    asm volatile(
        "mma.sync.aligned.m16n8k8.row.col.f32.tf32.tf32.f32 "
        "{%0,%1,%2,%3}, {%4,%5,%6,%7}, {%8,%9}, {%0,%1,%2,%3};\n"
        : "+f"(c[0]), "+f"(c[1]), "+f"(c[2]), "+f"(c[3])
        : "r"(a[0]), "r"(a[1]), "r"(a[2]), "r"(a[3]), "r"(b[0]), "r"(b[1]));
}

__device__ __forceinline__ float fast_sqrt(float v) {
    float r;
    asm("rsqrt.approx.f32 %0, %1;" : "=f"(r) : "f"(v));
    return v * r;   // sqrt(v) = v * rsqrt(v); v clamped >= 1e-12 upstream
}

// ---------------------------------------------------------------------------
// Fused symmetric dist+hinge: one 128x128 tile per block, upper triangle only.
// Each unordered pair (i<j) contributes BOTH anchor orientations.
__global__ __launch_bounds__(256)
void fused_kernel(const float* __restrict__ x, const int* __restrict__ tg,
                  const int* __restrict__ ni, int N, int D) {
    __shared__ float As[128][36];
    __shared__ float Bs[128][36];
    __shared__ float s_tA[128][8], s_tB[128][8];
    __shared__ float s_sqA[128], s_sqB[128];
    __shared__ int   s_lA[128], s_lB[128];
    __shared__ float s_red[3][8];
    __shared__ int   s_npos;

    const int tid  = threadIdx.x;
    const int lane = tid & 31;
    const int warp = tid >> 5;
    const int wm   = warp >> 2;
    const int wn   = warp & 3;
    const int g    = lane >> 2;
    const int q    = lane & 3;

    // decode triangular tile index (bx >= by)
    const int T = N >> 7;
    int by = 0, rem = blockIdx.x, rowlen = T;
    while (rem >= rowlen) { rem -= rowlen; by++; rowlen--; }
    const int bx = by + rem;
    const int rowBase = by * 128;
    const int colBase = bx * 128;
    const bool diag = (bx == by);

    if (tid == 0) s_npos = ni[0] - 1;
    if (tid < 128) {
        s_sqA[tid] = g_sq[rowBase + tid];
        s_sqB[tid] = g_sq[colBase + tid];
        s_lA[tid]  = tg[rowBase + tid];
        s_lB[tid]  = tg[colBase + tid];
    }
    {
        int r = tid >> 1, h = tid & 1;
        ((float4*)s_tA[r])[h] = ((const float4*)g_t[rowBase + r])[h];
        ((float4*)s_tB[r])[h] = ((const float4*)g_t[colBase + r])[h];
    }

    float acc[4][4][4];
    #pragma unroll
    for (int mt = 0; mt < 4; mt++)
        #pragma unroll
        for (int nt = 0; nt < 4; nt++)
            #pragma unroll
            for (int r = 0; r < 4; r++) acc[mt][nt][r] = 0.f;

    for (int kc = 0; kc < D; kc += 32) {
        __syncthreads();
        for (int t = tid; t < 128 * 8; t += 256) {
            int r  = t >> 3;
            int c4 = (t & 7) << 2;
            *(float4*)&As[r][c4] = *(const float4*)&x[(size_t)(rowBase + r) * D + kc + c4];
            *(float4*)&Bs[r][c4] = *(const float4*)&x[(size_t)(colBase + r) * D + kc + c4];
        }
        __syncthreads();

        #pragma unroll
        for (int kk = 0; kk < 32; kk += 8) {
            uint32_t a[4][4];
            #pragma unroll
            for (int mt = 0; mt < 4; mt++) {
                int r0 = wm * 64 + mt * 16 + g;
                a[mt][0] = __float_as_uint(As[r0][kk + q]);
                a[mt][1] = __float_as_uint(As[r0 + 8][kk + q]);
                a[mt][2] = __float_as_uint(As[r0][kk + q + 4]);
                a[mt][3] = __float_as_uint(As[r0 + 8][kk + q + 4]);
            }
            uint32_t b[4][2];
            #pragma unroll
            for (int nt = 0; nt < 4; nt++) {
                int c0 = wn * 32 + nt * 8 + g;
                b[nt][0] = __float_as_uint(Bs[c0][kk + q]);
                b[nt][1] = __float_as_uint(Bs[c0][kk + q + 4]);
            }
            #pragma unroll
            for (int mt = 0; mt < 4; mt++)
                #pragma unroll
                for (int nt = 0; nt < 4; nt++)
                    mma_tf32(acc[mt][nt], a[mt], b[nt]);
        }
    }
    __syncthreads();

    // -------------------- epilogue: hinge statistics --------------------
    const int npos = s_npos;
    // split accumulators to break FADD/FFMA dependency chains
    float sabsA0 = 0.f, sabsA1 = 0.f, sabsB0 = 0.f, sabsB1 = 0.f;
    float pcA = 0.f, pcB = 0.f;
    float dnacc = 0.f;

    if (npos == 7) {
        #pragma unroll
        for (int mt = 0; mt < 4; mt++) {
            #pragma unroll
            for (int h = 0; h < 2; h++) {
                const int r = wm * 64 + mt * 16 + h * 8 + g;
                const int i = rowBase + r;
                const float sqa = s_sqA[r];
                const int   la  = s_lA[r];
                float ta0 = s_tA[r][0], ta1 = s_tA[r][1], ta2 = s_tA[r][2];
                float ta3 = s_tA[r][3], ta4 = s_tA[r][4], ta5 = s_tA[r][5];
                float ta6 = s_tA[r][6];
                #pragma unroll
                for (int nt = 0; nt < 4; nt++) {
                    #pragma unroll
                    for (int v = 0; v < 2; v++) {
                        const int c = wn * 32 + nt * 8 + 2 * q + v;
                        const int j = colBase + c;
                        // validity mask: skip self-triangle on diag tiles + same-label
                        float m = ((diag && j <= i) || (la == s_lB[c])) ? 0.f : 1.f;
                        float d2 = fmaxf(sqa + s_sqB[c] - 2.f * acc[mt][nt][h * 2 + v], 1e-12f);
                        float d  = fast_sqrt(d2);
                        dnacc = fmaf(m, d, dnacc);
                        // a-side pairs (anchor = row i)
                        float dl;
                        dl = ta0 - d; sabsA0 = fmaf(m, fabsf(dl), sabsA0); if (dl < MARGIN) pcA += m;
                        dl = ta1 - d; sabsA1 = fmaf(m, fabsf(dl), sabsA1); if (dl < MARGIN) pcA += m;
                        dl = ta2 - d; sabsA0 = fmaf(m, fabsf(dl), sabsA0); if (dl < MARGIN) pcA += m;
                        dl = ta3 - d; sabsA1 = fmaf(m, fabsf(dl), sabsA1); if (dl < MARGIN) pcA += m;
                        dl = ta4 - d; sabsA0 = fmaf(m, fabsf(dl), sabsA0); if (dl < MARGIN) pcA += m;
                        dl = ta5 - d; sabsA1 = fmaf(m, fabsf(dl), sabsA1); if (dl < MARGIN) pcA += m;
                        dl = ta6 - d; sabsA0 = fmaf(m, fabsf(dl), sabsA0); if (dl < MARGIN) pcA += m;
                        // b-side pairs (anchor = col j)
                        dl = s_tB[c][0] - d; sabsB0 = fmaf(m, fabsf(dl), sabsB0); if (dl < MARGIN) pcB += m;
                        dl = s_tB[c][1] - d; sabsB1 = fmaf(m, fabsf(dl), sabsB1); if (dl < MARGIN) pcB += m;
                        dl = s_tB[c][2] - d; sabsB0 = fmaf(m, fabsf(dl), sabsB0); if (dl < MARGIN) pcB += m;
                        dl = s_tB[c][3] - d; sabsB1 = fmaf(m, fabsf(dl), sabsB1); if (dl < MARGIN) pcB += m;
                        dl = s_tB[c][4] - d; sabsB0 = fmaf(m, fabsf(dl), sabsB0); if (dl < MARGIN) pcB += m;
                        dl = s_tB[c][5] - d; sabsB1 = fmaf(m, fabsf(dl), sabsB1); if (dl < MARGIN) pcB += m;
                        dl = s_tB[c][6] - d; sabsB0 = fmaf(m, fabsf(dl), sabsB0); if (dl < MARGIN) pcB += m;
                    }
                }
            }
        }
    } else {
        // generic fallback
        #pragma unroll
        for (int mt = 0; mt < 4; mt++) {
            #pragma unroll
            for (int h = 0; h < 2; h++) {
                const int r = wm * 64 + mt * 16 + h * 8 + g;
                const int i = rowBase + r;
                #pragma unroll
                for (int nt = 0; nt < 4; nt++) {
                    #pragma unroll
                    for (int v = 0; v < 2; v++) {
                        const int c = wn * 32 + nt * 8 + 2 * q + v;
                        const int j = colBase + c;
                        float m = ((diag && j <= i) || (s_lA[r] == s_lB[c])) ? 0.f : 1.f;
                        float d2 = fmaxf(s_sqA[r] + s_sqB[c] - 2.f * acc[mt][nt][h * 2 + v], 1e-12f);
                        float d  = fast_sqrt(d2);
                        dnacc = fmaf(m, d, dnacc);
                        for (int p = 0; p < npos; p++) {
                            float dla = s_tA[r][p] - d;
                            sabsA0 = fmaf(m, fabsf(dla), sabsA0);
                            if (dla < MARGIN) pcA += m;
                            float dlb = s_tB[c][p] - d;
                            sabsB0 = fmaf(m, fabsf(dlb), sabsB0);
                            if (dlb < MARGIN) pcB += m;
                        }
                    }
                }
            }
        }
    }

    // block reduction of (sabs, dn*2, pc)
    float v3[3] = { (sabsA0 + sabsA1) + (sabsB0 + sabsB1),
                    2.f * dnacc,
                    pcA + pcB };
    #pragma unroll
    for (int r = 0; r < 3; r++) {
        float s = v3[r];
        #pragma unroll
        for (int o = 16; o > 0; o >>= 1) s += __shfl_xor_sync(0xffffffffu, s, o);
        if (lane == 0) s_red[r][warp] = s;
    }
    __syncthreads();
    if (warp == 0 && lane < 3) {
        float s = 0.f;
        #pragma unroll
        for (int w = 0; w < 8; w++) s += s_red[lane][w];
        atomicAdd(&g_acc[lane == 0 ? 0 : (lane == 1 ? 3 : 1)],
                  (double)s);  // lane0->sabs(0), lane1->dn(3), lane2->pc(1)
    }
}

// ---------------------------------------------------------------------------
__global__ __launch_bounds__(256)
void finalize_kernel(const int* __restrict__ ni, int N, float* __restrict__ out) {
    __shared__ double s_sum[8];
    const int tid  = threadIdx.x;
    const int lane = tid & 31;
    const int warp = tid >> 5;

    const float* __restrict__ tflat = (const float*)g_t;
    double s = 0.0;
    for (int t = tid; t < N * 8; t += 256) s += (double)tflat[t];
    #pragma unroll
    for (int o = 16; o > 0; o >>= 1) s += __shfl_xor_sync(0xffffffffu, s, o);
    if (lane == 0) s_sum[warp] = s;
    __syncthreads();

    if (tid == 0) {
        double T_total = 0.0;
        #pragma unroll
        for (int w = 0; w < 8; w++) T_total += s_sum[w];

        int K = ni[0];
        double npos = (double)(K - 1);
        double nneg = (double)(N - K);
        double sabs = g_acc[0];
        double pc   = g_acc[1];
        double dn   = g_acc[3];
        double possum = T_total - (double)N * npos * (double)MARGIN;
        double hinge  = 0.5 * (nneg * T_total - npos * dn + sabs);
        double cnt    = (double)N * npos * nneg;
        out[0] = (float)(hinge / cnt);
        out[1] = (float)(pc / cnt);
        out[2] = (float)(possum / ((double)N * npos));
        out[3] = (float)(dn / ((double)N * nneg));
    }
}

// ---------------------------------------------------------------------------
extern "C" void kernel_launch(void* const* d_in, const int* in_sizes, int n_in,
                              void* d_out, int out_size) {
    const float* x  = (const float*)d_in[0];
    const int*   tg = (const int*)d_in[1];
    const int*   ni = (const int*)d_in[2];
    float*       out = (float*)d_out;

    const int N = in_sizes[1];
    const int D = in_sizes[0] / N;
    const int T = N / 128;
    const int nTiles = T * (T + 1) / 2;

    prep_kernel<<<(N + 7) / 8, 256>>>(x, tg, ni, N, D);
    fused_kernel<<<nTiles, 256>>>(x, tg, ni, N, D);
    finalize_kernel<<<1, 256>>>(ni, N, out);
}

// round 7
// speedup vs baseline: 1.8557x; 1.4148x over previous
#include <cuda_runtime.h>
#include <cuda_bf16.h>
#include <cstdint>

#define MAXN 2048
#define MARGIN 0.2f

__device__ double   g_acc[4];   // [0]=sabs, [1]=prec_count, [2]=possum, [3]=dn
__device__ unsigned g_count;    // last-block-finalize counter (reset each run)

// ---------------------------------------------------------------------------
__device__ __forceinline__ void mma_tf32(float* c, const uint32_t* a, const uint32_t* b) {
    asm volatile(
        "mma.sync.aligned.m16n8k8.row.col.f32.tf32.tf32.f32 "
        "{%0,%1,%2,%3}, {%4,%5,%6,%7}, {%8,%9}, {%0,%1,%2,%3};\n"
        : "+f"(c[0]), "+f"(c[1]), "+f"(c[2]), "+f"(c[3])
        : "r"(a[0]), "r"(a[1]), "r"(a[2]), "r"(a[3]), "r"(b[0]), "r"(b[1]));
}

__device__ __forceinline__ float fast_sqrt(float v) {
    float r;
    asm("rsqrt.approx.f32 %0, %1;" : "=f"(r) : "f"(v));
    return v * r;   // v clamped >= 1e-12 upstream
}

// ---------------------------------------------------------------------------
// Single-launch fused kernel: symmetric 128x128 tiles (upper triangle).
// Positive distances & norms computed in-block from the staged tiles
// (labels are grouped in aligned 8-blocks, so positives are tile-local).
// Last block to finish performs finalization and resets global state.
__global__ __launch_bounds__(256)
void fused_kernel(const float* __restrict__ x, const int* __restrict__ tg,
                  const int* __restrict__ ni, int N, int D, int nBlocks,
                  float* __restrict__ out) {
    __shared__ float As[128][36];
    __shared__ float Bs[128][36];
    __shared__ float s_tA[128][8], s_tB[128][8];
    __shared__ float s_sqA[128], s_sqB[128];
    __shared__ int   s_lA[128], s_lB[128];
    __shared__ float s_red[4][8];

    // post-GEMM scratch aliased onto the (dead) A/B tiles
    float (*s_dotA)[8][8] = (float (*)[8][8])&As[0][0];   // [16][8][8]
    float (*s_dotB)[8][8] = (float (*)[8][8])&Bs[0][0];

    const int tid  = threadIdx.x;
    const int lane = tid & 31;
    const int warp = tid >> 5;
    const int wm   = warp >> 2;
    const int wn   = warp & 3;
    const int g    = lane >> 2;
    const int q    = lane & 3;

    // decode triangular tile index (bx >= by)
    const int T = N >> 7;
    int by = 0, rem = blockIdx.x, rowlen = T;
    while (rem >= rowlen) { rem -= rowlen; by++; rowlen--; }
    const int bx = by + rem;
    const int rowBase = by * 128;
    const int colBase = bx * 128;
    const bool diag = (bx == by);

    if (tid < 128) {
        s_lA[tid] = tg[rowBase + tid];
        s_lB[tid] = tg[colBase + tid];
    }

    // pos-pair assignment: 1024 ordered pairs per side, 4 consecutive per thread
    // p0 = tid*4: gp = group (0..15), a = row-in-group, b0 = col-in-group base (0 or 4)
    const int p0  = tid * 4;
    const int pgp = p0 >> 6;
    const int pa  = (p0 >> 3) & 7;
    const int pb0 = p0 & 7;
    const int iA  = pgp * 8 + pa;

    float acc[4][4][4];
    #pragma unroll
    for (int mt = 0; mt < 4; mt++)
        #pragma unroll
        for (int nt = 0; nt < 4; nt++)
            #pragma unroll
            for (int r = 0; r < 4; r++) acc[mt][nt][r] = 0.f;

    float dotA[4] = {0.f, 0.f, 0.f, 0.f};
    float dotB[4] = {0.f, 0.f, 0.f, 0.f};

    for (int kc = 0; kc < D; kc += 32) {
        __syncthreads();
        for (int t = tid; t < 128 * 8; t += 256) {
            int r  = t >> 3;
            int c4 = (t & 7) << 2;
            *(float4*)&As[r][c4] = *(const float4*)&x[(size_t)(rowBase + r) * D + kc + c4];
            *(float4*)&Bs[r][c4] = *(const float4*)&x[(size_t)(colBase + r) * D + kc + c4];
        }
        __syncthreads();

        // ---- tensor-core GEMM on the chunk ----
        #pragma unroll
        for (int kk = 0; kk < 32; kk += 8) {
            uint32_t a[4][4];
            #pragma unroll
            for (int mt = 0; mt < 4; mt++) {
                int r0 = wm * 64 + mt * 16 + g;
                a[mt][0] = __float_as_uint(As[r0][kk + q]);
                a[mt][1] = __float_as_uint(As[r0 + 8][kk + q]);
                a[mt][2] = __float_as_uint(As[r0][kk + q + 4]);
                a[mt][3] = __float_as_uint(As[r0 + 8][kk + q + 4]);
            }
            uint32_t b[4][2];
            #pragma unroll
            for (int nt = 0; nt < 4; nt++) {
                int c0 = wn * 32 + nt * 8 + g;
                b[nt][0] = __float_as_uint(Bs[c0][kk + q]);
                b[nt][1] = __float_as_uint(Bs[c0][kk + q + 4]);
            }
            #pragma unroll
            for (int mt = 0; mt < 4; mt++)
                #pragma unroll
                for (int nt = 0; nt < 4; nt++)
                    mma_tf32(acc[mt][nt], a[mt], b[nt]);
        }

        // ---- intra-group positive dot partials (fp32 scalar) ----
        #pragma unroll
        for (int k4 = 0; k4 < 8; k4++) {
            float4 av = *(const float4*)&As[iA][k4 * 4];
            float4 bv = *(const float4*)&Bs[iA][k4 * 4];
            #pragma unroll
            for (int jj = 0; jj < 4; jj++) {
                float4 aj = *(const float4*)&As[pgp * 8 + pb0 + jj][k4 * 4];
                dotA[jj] = fmaf(av.x, aj.x, fmaf(av.y, aj.y, fmaf(av.z, aj.z, fmaf(av.w, aj.w, dotA[jj]))));
                float4 bj = *(const float4*)&Bs[pgp * 8 + pb0 + jj][k4 * 4];
                dotB[jj] = fmaf(bv.x, bj.x, fmaf(bv.y, bj.y, fmaf(bv.z, bj.z, fmaf(bv.w, bj.w, dotB[jj]))));
            }
        }
    }
    __syncthreads();

    // publish pos dots into aliased scratch (tiles now dead)
    #pragma unroll
    for (int jj = 0; jj < 4; jj++) {
        s_dotA[pgp][pa][pb0 + jj] = dotA[jj];
        s_dotB[pgp][pa][pb0 + jj] = dotB[jj];
    }
    __syncthreads();

    // fill t-tables + norms: tid<128 -> rows, tid>=128 -> cols
    float psum = 0.f;
    {
        const int r   = tid & 127;
        const int gp2 = r >> 3;
        const int a2  = r & 7;
        float (*dot)[8][8] = (tid < 128) ? s_dotA : s_dotB;
        float (*tarr)[8]   = (tid < 128) ? s_tA   : s_tB;
        float sqa = dot[gp2][a2][a2];
        if (tid < 128) s_sqA[r] = sqa; else s_sqB[r] = sqa;
        int idx = 0;
        #pragma unroll
        for (int j = 0; j < 8; j++) {
            if (j != a2) {
                float d2 = fmaxf(sqa + dot[gp2][j][j] - 2.f * dot[gp2][a2][j], 1e-12f);
                float d  = fast_sqrt(d2);
                tarr[r][idx++] = d + MARGIN;
                if (diag && tid < 128) psum += d;   // possum counted once per anchor (diag tiles)
            }
        }
        tarr[r][7] = 0.f;
    }
    __syncthreads();

    // -------------------- epilogue: hinge statistics --------------------
    float sabsA0 = 0.f, sabsA1 = 0.f, sabsB0 = 0.f, sabsB1 = 0.f;
    float pcA = 0.f, pcB = 0.f;
    float dnacc = 0.f;

    #pragma unroll
    for (int mt = 0; mt < 4; mt++) {
        #pragma unroll
        for (int h = 0; h < 2; h++) {
            const int r = wm * 64 + mt * 16 + h * 8 + g;
            const int i = rowBase + r;
            const float sqa = s_sqA[r];
            const int   la  = s_lA[r];
            float ta0 = s_tA[r][0], ta1 = s_tA[r][1], ta2 = s_tA[r][2];
            float ta3 = s_tA[r][3], ta4 = s_tA[r][4], ta5 = s_tA[r][5];
            float ta6 = s_tA[r][6];
            #pragma unroll
            for (int nt = 0; nt < 4; nt++) {
                #pragma unroll
                for (int v = 0; v < 2; v++) {
                    const int c = wn * 32 + nt * 8 + 2 * q + v;
                    const int j = colBase + c;
                    float m = ((diag && j <= i) || (la == s_lB[c])) ? 0.f : 1.f;
                    float d2 = fmaxf(sqa + s_sqB[c] - 2.f * acc[mt][nt][h * 2 + v], 1e-12f);
                    float d  = fast_sqrt(d2);
                    dnacc = fmaf(m, d, dnacc);
                    float dl;
                    dl = ta0 - d; sabsA0 = fmaf(m, fabsf(dl), sabsA0); if (dl < MARGIN) pcA += m;
                    dl = ta1 - d; sabsA1 = fmaf(m, fabsf(dl), sabsA1); if (dl < MARGIN) pcA += m;
                    dl = ta2 - d; sabsA0 = fmaf(m, fabsf(dl), sabsA0); if (dl < MARGIN) pcA += m;
                    dl = ta3 - d; sabsA1 = fmaf(m, fabsf(dl), sabsA1); if (dl < MARGIN) pcA += m;
                    dl = ta4 - d; sabsA0 = fmaf(m, fabsf(dl), sabsA0); if (dl < MARGIN) pcA += m;
                    dl = ta5 - d; sabsA1 = fmaf(m, fabsf(dl), sabsA1); if (dl < MARGIN) pcA += m;
                    dl = ta6 - d; sabsA0 = fmaf(m, fabsf(dl), sabsA0); if (dl < MARGIN) pcA += m;
                    dl = s_tB[c][0] - d; sabsB0 = fmaf(m, fabsf(dl), sabsB0); if (dl < MARGIN) pcB += m;
                    dl = s_tB[c][1] - d; sabsB1 = fmaf(m, fabsf(dl), sabsB1); if (dl < MARGIN) pcB += m;
                    dl = s_tB[c][2] - d; sabsB0 = fmaf(m, fabsf(dl), sabsB0); if (dl < MARGIN) pcB += m;
                    dl = s_tB[c][3] - d; sabsB1 = fmaf(m, fabsf(dl), sabsB1); if (dl < MARGIN) pcB += m;
                    dl = s_tB[c][4] - d; sabsB0 = fmaf(m, fabsf(dl), sabsB0); if (dl < MARGIN) pcB += m;
                    dl = s_tB[c][5] - d; sabsB1 = fmaf(m, fabsf(dl), sabsB1); if (dl < MARGIN) pcB += m;
                    dl = s_tB[c][6] - d; sabsB0 = fmaf(m, fabsf(dl), sabsB0); if (dl < MARGIN) pcB += m;
                }
            }
        }
    }

    // block reduction of (sabs, dn*2, pc, psum)
    float v4[4] = { (sabsA0 + sabsA1) + (sabsB0 + sabsB1),
                    2.f * dnacc,
                    pcA + pcB,
                    psum };
    #pragma unroll
    for (int r = 0; r < 4; r++) {
        float s = v4[r];
        #pragma unroll
        for (int o = 16; o > 0; o >>= 1) s += __shfl_xor_sync(0xffffffffu, s, o);
        if (lane == 0) s_red[r][warp] = s;
    }
    __syncthreads();

    if (warp == 0) {
        if (lane < 4) {
            float s = 0.f;
            #pragma unroll
            for (int w = 0; w < 8; w++) s += s_red[lane][w];
            // lane0->sabs(0), lane1->dn(3), lane2->pc(1), lane3->possum(2)
            const int dst[4] = {0, 3, 1, 2};
            atomicAdd(&g_acc[dst[lane]], (double)s);
        }
        __syncwarp();
        if (lane == 0) {
            __threadfence();
            unsigned old = atomicAdd(&g_count, 1u);
            if (old == (unsigned)(nBlocks - 1)) {
                // last block: all other blocks' g_acc atomics are visible
                double sabs   = atomicAdd(&g_acc[0], 0.0);
                double pc     = atomicAdd(&g_acc[1], 0.0);
                double possum = atomicAdd(&g_acc[2], 0.0);
                double dn     = atomicAdd(&g_acc[3], 0.0);
                int K = ni[0];
                double npos = (double)(K - 1);
                double nneg = (double)(N - K);
                double T_total = possum + (double)N * npos * (double)MARGIN;
                double hinge   = 0.5 * (nneg * T_total - npos * dn + sabs);
                double cnt     = (double)N * npos * nneg;
                out[0] = (float)(hinge / cnt);
                out[1] = (float)(pc / cnt);
                out[2] = (float)(possum / ((double)N * npos));
                out[3] = (float)(dn / ((double)N * nneg));
                // reset state for next graph replay
                g_acc[0] = 0.0; g_acc[1] = 0.0; g_acc[2] = 0.0; g_acc[3] = 0.0;
                __threadfence();
                g_count = 0u;
            }
        }
    }
}

// ---------------------------------------------------------------------------
extern "C" void kernel_launch(void* const* d_in, const int* in_sizes, int n_in,
                              void* d_out, int out_size) {
    const float* x  = (const float*)d_in[0];
    const int*   tg = (const int*)d_in[1];
    const int*   ni = (const int*)d_in[2];
    float*       out = (float*)d_out;

    const int N = in_sizes[1];
    const int D = in_sizes[0] / N;
    const int T = N / 128;
    const int nTiles = T * (T + 1) / 2;

    fused_kernel<<<nTiles, 256>>>(x, tg, ni, N, D, nTiles, out);
}